// round 2
// baseline (speedup 1.0000x reference)
#include <cuda_runtime.h>

// Sobel magnitude: out = sqrt(gx^2 + gy^2 + 1e-4), 3x3 cross-correlation,
// zero padding, x: [64, 1, 512, 512] fp32.
// kx = [[1,0,-1],[2,0,-2],[1,0,-1]]/4 ; ky = [[1,2,1],[0,0,0],[-1,-2,-1]]/4
//
// Separable form:
//   a[j] = v0[j] + 2*v1[j] + v2[j]   (vertical smooth)  -> gx*4 = a[k] - a[k+2]
//   b[j] = v0[j] - v2[j]             (vertical diff)    -> gy*4 = b[k] + 2*b[k+1] + b[k+2]
//   out  = 0.25 * sqrt(gx4^2 + gy4^2 + 16*eps)

#define W 512
#define H 512
#define EPS16 1.6e-3f   // 16 * 1e-4

__device__ __forceinline__ float fast_sqrt(float x) {
    float r;
    asm("sqrt.approx.f32 %0, %1;" : "=f"(r) : "f"(x));
    return r;
}

// 8 outputs per thread. blockDim = (64, 4): 64 threads * 8 px = full 512 row.
__global__ __launch_bounds__(256) void sobel_kernel(
    const float* __restrict__ in, float* __restrict__ out)
{
    const int ox = threadIdx.x * 8;                 // 0..504, float4 aligned
    const int oy = blockIdx.y * 4 + threadIdx.y;    // 0..511
    const long long img = (long long)blockIdx.z * (W * H);
    const float* base = in + img;

    // v[r][0..9] = cols ox-1 .. ox+8 of row oy-1+r (zero outside image)
    float v[3][10];

    #pragma unroll
    for (int r = 0; r < 3; ++r) {
        const int y = oy - 1 + r;
        if (y >= 0 && y < H) {
            const float* row = base + y * W;
            const float4 c0 = *reinterpret_cast<const float4*>(row + ox);
            const float4 c1 = *reinterpret_cast<const float4*>(row + ox + 4);
            v[r][1] = c0.x; v[r][2] = c0.y; v[r][3] = c0.z; v[r][4] = c0.w;
            v[r][5] = c1.x; v[r][6] = c1.y; v[r][7] = c1.z; v[r][8] = c1.w;
            v[r][0] = (ox > 0)     ? __ldg(row + ox - 1) : 0.0f;
            v[r][9] = (ox + 8 < W) ? __ldg(row + ox + 8) : 0.0f;
        } else {
            #pragma unroll
            for (int j = 0; j < 10; ++j) v[r][j] = 0.0f;
        }
    }

    // Per-column vertical combinations (amortized across 8 outputs)
    float a[10], b[10];
    #pragma unroll
    for (int j = 0; j < 10; ++j) {
        a[j] = fmaf(2.0f, v[1][j], v[0][j] + v[2][j]);
        b[j] = v[0][j] - v[2][j];
    }

    float o[8];
    #pragma unroll
    for (int k = 0; k < 8; ++k) {
        const float gx4 = a[k] - a[k + 2];
        const float gy4 = fmaf(2.0f, b[k + 1], b[k] + b[k + 2]);
        o[k] = 0.25f * fast_sqrt(fmaf(gx4, gx4, fmaf(gy4, gy4, EPS16)));
    }

    float* op = out + img + oy * W + ox;
    *reinterpret_cast<float4*>(op)     = make_float4(o[0], o[1], o[2], o[3]);
    *reinterpret_cast<float4*>(op + 4) = make_float4(o[4], o[5], o[6], o[7]);
}

extern "C" void kernel_launch(void* const* d_in, const int* in_sizes, int n_in,
                              void* d_out, int out_size)
{
    const float* x = (const float*)d_in[0];
    float* out = (float*)d_out;

    dim3 block(64, 4, 1);            // 256 threads, full row width per y-slice
    dim3 grid(1, H / 4, 64);         // 1 x 128 x 64
    sobel_kernel<<<grid, block>>>(x, out);
}

// round 3
// speedup vs baseline: 1.0363x; 1.0363x over previous
#include <cuda_runtime.h>

// Sobel magnitude: out = sqrt(gx^2 + gy^2 + 1e-4), 3x3 cross-correlation,
// zero padding, x: [64, 1, 512, 512] fp32.
// kx = [[1,0,-1],[2,0,-2],[1,0,-1]]/4 ; ky = [[1,2,1],[0,0,0],[-1,-2,-1]]/4
//
// Separable: a[j]=t+2m+b (-> gx4 = a[k]-a[k+2]); b[j]=t-b (-> gy4 = b[k]+2b[k+1]+b[k+2])
// out = 0.25 * sqrt(gx4^2 + gy4^2 + 16e-4)
//
// Layout: blockDim=(32,8). One warp spans 256 px (8 px/thread); halos via
// warp shuffle (edge lanes only do a scalar load). Each thread produces 4
// output rows from a 3-row sliding register window: 6 row-loads / 4 rows out.

#define W 512
#define H 512
#define EPS16 1.6e-3f
#define ROWS 4

__device__ __forceinline__ float fast_sqrt(float x) {
    float r;
    asm("sqrt.approx.f32 %0, %1;" : "=f"(r) : "f"(x));
    return r;
}

// Load 10-wide window (cols ox-1 .. ox+8) of row y into c[0..9].
// y is uniform across the warp (blockDim.x == 32), so branches are safe
// around the shuffles.
__device__ __forceinline__ void load_row(const float* __restrict__ base,
                                         int y, int ox, int lane, float* c)
{
    if (y < 0 || y >= H) {
        #pragma unroll
        for (int j = 0; j < 10; ++j) c[j] = 0.0f;
        return;
    }
    const float* row = base + y * W;
    const float4 p = *reinterpret_cast<const float4*>(row + ox);
    const float4 q = *reinterpret_cast<const float4*>(row + ox + 4);
    c[1] = p.x; c[2] = p.y; c[3] = p.z; c[4] = p.w;
    c[5] = q.x; c[6] = q.y; c[7] = q.z; c[8] = q.w;
    c[0] = __shfl_up_sync(0xffffffffu, c[8], 1);    // left lane's px7
    c[9] = __shfl_down_sync(0xffffffffu, c[1], 1);  // right lane's px0
    if (lane == 0)  c[0] = (ox > 0)     ? __ldg(row + ox - 1) : 0.0f;
    if (lane == 31) c[9] = (ox + 8 < W) ? __ldg(row + ox + 8) : 0.0f;
}

__global__ __launch_bounds__(256) void sobel_kernel(
    const float* __restrict__ in, float* __restrict__ out)
{
    const int lane = threadIdx.x;                                   // 0..31
    const int ox = (blockIdx.x * 32 + lane) * 8;                    // 0..504
    const int oy0 = (blockIdx.y * 8 + threadIdx.y) * ROWS;          // 0..508
    const long long img = (long long)blockIdx.z * (W * H);
    const float* base = in + img;
    float* obase = out + img;

    float r[3][10];
    load_row(base, oy0 - 1, ox, lane, r[0]);
    load_row(base, oy0,     ox, lane, r[1]);

    #pragma unroll
    for (int i = 0; i < ROWS; ++i) {
        const int t = i % 3;             // top row buffer
        const int m = (i + 1) % 3;       // mid
        const int bo = (i + 2) % 3;      // bottom (loaded now)
        load_row(base, oy0 + 1 + i, ox, lane, r[bo]);

        float a[10], b[10];
        #pragma unroll
        for (int j = 0; j < 10; ++j) {
            a[j] = fmaf(2.0f, r[m][j], r[t][j] + r[bo][j]);
            b[j] = r[t][j] - r[bo][j];
        }

        float o[8];
        #pragma unroll
        for (int k = 0; k < 8; ++k) {
            const float gx4 = a[k] - a[k + 2];
            const float gy4 = fmaf(2.0f, b[k + 1], b[k] + b[k + 2]);
            o[k] = 0.25f * fast_sqrt(fmaf(gx4, gx4, fmaf(gy4, gy4, EPS16)));
        }

        float* op = obase + (oy0 + i) * W + ox;
        *reinterpret_cast<float4*>(op)     = make_float4(o[0], o[1], o[2], o[3]);
        *reinterpret_cast<float4*>(op + 4) = make_float4(o[4], o[5], o[6], o[7]);
    }
}

extern "C" void kernel_launch(void* const* d_in, const int* in_sizes, int n_in,
                              void* d_out, int out_size)
{
    const float* x = (const float*)d_in[0];
    float* out = (float*)d_out;

    dim3 block(32, 8, 1);                        // 256 threads
    dim3 grid(W / (32 * 8), H / (8 * ROWS), 64); // 2 x 16 x 64 = 2048 CTAs
    sobel_kernel<<<grid, block>>>(x, out);
}